// round 1
// baseline (speedup 1.0000x reference)
#include <cuda_runtime.h>
#include <math.h>

#define B_  2048
#define H_  4
#define D_  4096
#define M_  8
#define DM_ 512   // D_/M_

// Scratch for grouped activations Y (row-major 2048 x 4096).
// Group-major flatten of (m, b, c) == row-major (B_, D_) flat order.
__device__ __align__(16) float g_Y[(size_t)B_ * D_];

// ---------------------------------------------------------------------------
// Kernel 1: Y[flat] = sum_h x[b, h, m*DM_+c] * local_W[m,h] + local_b[m]
// where flat = (m*B_ + b)*DM_ + c. One float4 per thread (DM_ % 4 == 0, so a
// float4 never crosses a (m,b) boundary).
// ---------------------------------------------------------------------------
__global__ void compute_y_kernel(const float* __restrict__ x,
                                 const float* __restrict__ lW,
                                 const float* __restrict__ lb) {
    long long i4 = (long long)blockIdx.x * blockDim.x + threadIdx.x;
    long long flat = i4 * 4;
    if (flat >= (long long)B_ * D_) return;

    int c = (int)(flat % DM_);
    long long t = flat / DM_;
    int b = (int)(t % B_);
    int m = (int)(t / B_);

    float w0 = lW[m * H_ + 0];
    float w1 = lW[m * H_ + 1];
    float w2 = lW[m * H_ + 2];
    float w3 = lW[m * H_ + 3];
    float bb = lb[m];

    const float* xb = x + (long long)b * H_ * D_ + m * DM_ + c;
    float4 v0 = *(const float4*)(xb + 0ll * D_);
    float4 v1 = *(const float4*)(xb + 1ll * D_);
    float4 v2 = *(const float4*)(xb + 2ll * D_);
    float4 v3 = *(const float4*)(xb + 3ll * D_);

    float4 r;
    r.x = fmaf(w0, v0.x, fmaf(w1, v1.x, fmaf(w2, v2.x, fmaf(w3, v3.x, bb))));
    r.y = fmaf(w0, v0.y, fmaf(w1, v1.y, fmaf(w2, v2.y, fmaf(w3, v3.y, bb))));
    r.z = fmaf(w0, v0.z, fmaf(w1, v1.z, fmaf(w2, v2.z, fmaf(w3, v3.z, bb))));
    r.w = fmaf(w0, v0.w, fmaf(w1, v1.w, fmaf(w2, v2.w, fmaf(w3, v3.w, bb))));

    *(float4*)&g_Y[flat] = r;
}

// ---------------------------------------------------------------------------
// Kernel 2: out[r, n] = sigmoid( dot(Y[r, :], W[n, :]) + bias[n] )
// Both operands K-contiguous (NT gemm). 128x128 block tile, KT=8,
// 256 threads, 8x8 register tile per thread.
// ---------------------------------------------------------------------------
__global__ __launch_bounds__(256, 2)
void gemm_bias_sigmoid_kernel(const float* __restrict__ W,
                              const float* __restrict__ bias,
                              float* __restrict__ out) {
    __shared__ float As[8][128];  // As[k][i] = Y[row0+i, k0+k]
    __shared__ float Bs[8][128];  // Bs[k][j] = W[col0+j, k0+k]

    const int tid  = threadIdx.x;
    const int row0 = blockIdx.y * 128;
    const int col0 = blockIdx.x * 128;

    // load mapping: one float4 of A and one of B per thread per k-step
    const int lr = tid >> 1;          // 0..127 : tile row
    const int lk = (tid & 1) << 2;    // 0 or 4 : k offset

    // compute mapping: 16x16 thread grid, 8x8 outputs each
    const int tx = tid & 15;
    const int ty = tid >> 4;

    const float* Aptr = g_Y + (long long)(row0 + lr) * D_ + lk;
    const float* Bptr = W   + (long long)(col0 + lr) * D_ + lk;

    float acc[8][8];
#pragma unroll
    for (int i = 0; i < 8; i++)
#pragma unroll
        for (int j = 0; j < 8; j++) acc[i][j] = 0.0f;

    for (int k0 = 0; k0 < D_; k0 += 8) {
        float4 av = *(const float4*)(Aptr + k0);
        float4 bv = *(const float4*)(Bptr + k0);

        __syncthreads();  // previous iteration's reads done
        As[lk + 0][lr] = av.x; As[lk + 1][lr] = av.y;
        As[lk + 2][lr] = av.z; As[lk + 3][lr] = av.w;
        Bs[lk + 0][lr] = bv.x; Bs[lk + 1][lr] = bv.y;
        Bs[lk + 2][lr] = bv.z; Bs[lk + 3][lr] = bv.w;
        __syncthreads();

#pragma unroll
        for (int k = 0; k < 8; k++) {
            float ar[8], br[8];
            *(float4*)&ar[0] = *(const float4*)&As[k][ty * 8];
            *(float4*)&ar[4] = *(const float4*)&As[k][ty * 8 + 4];
            *(float4*)&br[0] = *(const float4*)&Bs[k][tx * 8];
            *(float4*)&br[4] = *(const float4*)&Bs[k][tx * 8 + 4];
#pragma unroll
            for (int i = 0; i < 8; i++)
#pragma unroll
                for (int j = 0; j < 8; j++)
                    acc[i][j] = fmaf(ar[i], br[j], acc[i][j]);
        }
    }

    // epilogue: bias + sigmoid
#pragma unroll
    for (int i = 0; i < 8; i++) {
        const int r = row0 + ty * 8 + i;
#pragma unroll
        for (int j = 0; j < 8; j++) {
            const int ccol = col0 + tx * 8 + j;
            float v = acc[i][j] + bias[ccol];
            out[(long long)r * D_ + ccol] = 1.0f / (1.0f + expf(-v));
        }
    }
}

// ---------------------------------------------------------------------------
// launch
// ---------------------------------------------------------------------------
extern "C" void kernel_launch(void* const* d_in, const int* in_sizes, int n_in,
                              void* d_out, int out_size) {
    const float* x  = (const float*)d_in[0];  // (2048, 4, 4096)
    const float* lW = (const float*)d_in[1];  // (8, 4)
    const float* lb = (const float*)d_in[2];  // (8,)
    const float* pW = (const float*)d_in[3];  // (4096, 4096)
    const float* pb = (const float*)d_in[4];  // (4096,)
    float* out = (float*)d_out;               // (2048, 4096)

    // Kernel 1: build Y
    {
        long long n4 = (long long)B_ * D_ / 4;
        int threads = 256;
        int blocks = (int)((n4 + threads - 1) / threads);
        compute_y_kernel<<<blocks, threads>>>(x, lW, lb);
    }

    // Kernel 2: GEMM + bias + sigmoid
    {
        dim3 grid(D_ / 128, B_ / 128);  // (32, 16)
        gemm_bias_sigmoid_kernel<<<grid, 256>>>(pW, pb, out);
    }
}

// round 3
// speedup vs baseline: 4.0223x; 4.0223x over previous
#include <cuda_runtime.h>
#include <cstdint>
#include <math.h>

#define B_  2048
#define H_  4
#define D_  4096
#define M_  8
#define DM_ 512

// ---------------- scratch ----------------
__device__ __align__(16) float g_Y[(size_t)B_ * D_];        // tf32-rounded activations
__device__ __align__(16) float g_Wt[(size_t)D_ * D_];       // tf32-rounded proj_W

// ---------------- helpers ----------------
__device__ __forceinline__ uint32_t smem_u32(const void* p) {
    uint32_t a;
    asm("{ .reg .u64 t; cvta.to.shared.u64 t, %1; cvt.u32.u64 %0, t; }" : "=r"(a) : "l"(p));
    return a;
}

__device__ __forceinline__ float tf32_rna(float v) {
    uint32_t b;
    asm("cvt.rna.tf32.f32 %0, %1;" : "=r"(b) : "f"(v));
    return __uint_as_float(b);
}

#define CP_ASYNC16(dst, src) \
    asm volatile("cp.async.cg.shared.global [%0], [%1], 16;" :: "r"(dst), "l"(src))
#define CP_COMMIT()  asm volatile("cp.async.commit_group;" ::: "memory")
#define CP_WAIT0()   asm volatile("cp.async.wait_group 0;" ::: "memory")

#define LDSM_X4(r, addr) \
    asm volatile("ldmatrix.sync.aligned.m8n8.x4.shared.b16 {%0,%1,%2,%3}, [%4];" \
                 : "=r"((r)[0]), "=r"((r)[1]), "=r"((r)[2]), "=r"((r)[3]) : "r"(addr))

__device__ __forceinline__ void mma_tf32(float* d, const uint32_t* a, const uint32_t* b) {
    asm volatile(
        "mma.sync.aligned.m16n8k8.row.col.f32.tf32.tf32.f32 "
        "{%0,%1,%2,%3}, {%4,%5,%6,%7}, {%8,%9}, {%0,%1,%2,%3};"
        : "+f"(d[0]), "+f"(d[1]), "+f"(d[2]), "+f"(d[3])
        : "r"(a[0]), "r"(a[1]), "r"(a[2]), "r"(a[3]), "r"(b[0]), "r"(b[1]));
}

__device__ __forceinline__ float sigmoidf_(float v) {
    return 1.0f / (1.0f + expf(-v));
}

// ---------------- kernel 0: tf32-round proj_W into scratch ----------------
__global__ void conv_w_kernel(const float* __restrict__ W) {
    long long i4 = (long long)blockIdx.x * blockDim.x + threadIdx.x;
    long long base = i4 * 4;
    if (base >= (long long)D_ * D_) return;
    float4 v = *(const float4*)(W + base);
    v.x = tf32_rna(v.x); v.y = tf32_rna(v.y);
    v.z = tf32_rna(v.z); v.w = tf32_rna(v.w);
    *(float4*)(g_Wt + base) = v;
}

// ---------------- kernel 1: grouped local linear (tf32-rounded output) -----
__global__ void compute_y_kernel(const float* __restrict__ x,
                                 const float* __restrict__ lW,
                                 const float* __restrict__ lb) {
    long long i4 = (long long)blockIdx.x * blockDim.x + threadIdx.x;
    long long flat = i4 * 4;
    if (flat >= (long long)B_ * D_) return;

    int c = (int)(flat % DM_);
    long long t = flat / DM_;
    int b = (int)(t % B_);
    int m = (int)(t / B_);

    float w0 = lW[m * H_ + 0], w1 = lW[m * H_ + 1];
    float w2 = lW[m * H_ + 2], w3 = lW[m * H_ + 3];
    float bb = lb[m];

    const float* xb = x + (long long)b * H_ * D_ + m * DM_ + c;
    float4 v0 = *(const float4*)(xb + 0ll * D_);
    float4 v1 = *(const float4*)(xb + 1ll * D_);
    float4 v2 = *(const float4*)(xb + 2ll * D_);
    float4 v3 = *(const float4*)(xb + 3ll * D_);

    float4 r;
    r.x = fmaf(w0, v0.x, fmaf(w1, v1.x, fmaf(w2, v2.x, fmaf(w3, v3.x, bb))));
    r.y = fmaf(w0, v0.y, fmaf(w1, v1.y, fmaf(w2, v2.y, fmaf(w3, v3.y, bb))));
    r.z = fmaf(w0, v0.z, fmaf(w1, v1.z, fmaf(w2, v2.z, fmaf(w3, v3.z, bb))));
    r.w = fmaf(w0, v0.w, fmaf(w1, v1.w, fmaf(w2, v2.w, fmaf(w3, v3.w, bb))));

    r.x = tf32_rna(r.x); r.y = tf32_rna(r.y);
    r.z = tf32_rna(r.z); r.w = tf32_rna(r.w);
    *(float4*)&g_Y[flat] = r;
}

// ---------------- kernel 2: tf32 mma.sync GEMM + bias + sigmoid ----------
// C[2048 x 4096] = sigmoid( Y @ W^T + bias ), NT gemm, both K-contiguous.
#define TM      128
#define TN      128
#define KC      32
#define NCHUNK  (D_ / KC)          // 128
#define SROW    36                 // padded row stride in floats (144 B)
#define AS_F    (128 * SROW)       // floats per stage per operand (4608)
#define SM_BYTES (4 * AS_F * 4)    // 73728

__global__ __launch_bounds__(256, 2)
void gemm_mma_kernel(const float* __restrict__ bias,
                     float* __restrict__ out) {
    extern __shared__ float sm[];
    const uint32_t smb = smem_u32(sm);

    const int tid  = threadIdx.x;
    const int wid  = tid >> 5;
    const int lane = tid & 31;
    const int wm   = wid >> 2;     // 0..1
    const int wn   = wid & 3;      // 0..3

    const int row0 = blockIdx.y * TM;
    const int col0 = blockIdx.x * TN;

    const float* Ag = g_Y  + (long long)row0 * D_;
    const float* Bg = g_Wt + (long long)col0 * D_;

    // ---- per-thread ldmatrix offsets (floats, k-part added per step) ----
    int a_off[4], b_off[2];
#pragma unroll
    for (int am = 0; am < 4; am++)
        a_off[am] = (wm * 64 + am * 16 + (lane & 15)) * SROW + ((lane >> 4) << 2);
    {
        const int seg = lane >> 3;
#pragma unroll
        for (int bn = 0; bn < 2; bn++)
            b_off[bn] = (wn * 32 + bn * 16 + ((seg >> 1) << 3) + (lane & 7)) * SROW
                      + ((seg & 1) << 2);
    }

    // ---- gmem->smem load offsets: 4 float4 each for A and B ----
    const int lrow = tid >> 3;       // 0..31 (base, +32 per i)
    const int lc4  = tid & 7;        // float4 col

    float d[4][4][4];
#pragma unroll
    for (int i = 0; i < 4; i++)
#pragma unroll
        for (int j = 0; j < 4; j++)
#pragma unroll
            for (int q = 0; q < 4; q++) d[i][j][q] = 0.0f;

    // ---- async load of one K-chunk into stage s ----
    auto load_chunk = [&](int it, int s) {
        const int k0 = it * KC;
        const uint32_t aS = smb + (uint32_t)(s * AS_F) * 4;
        const uint32_t bS = smb + (uint32_t)((2 + s) * AS_F) * 4;
#pragma unroll
        for (int i = 0; i < 4; i++) {
            const int r = lrow + i * 32;
            CP_ASYNC16(aS + (uint32_t)(r * SROW + lc4 * 4) * 4,
                       Ag + (long long)r * D_ + k0 + lc4 * 4);
        }
#pragma unroll
        for (int i = 0; i < 4; i++) {
            const int r = lrow + i * 32;
            CP_ASYNC16(bS + (uint32_t)(r * SROW + lc4 * 4) * 4,
                       Bg + (long long)r * D_ + k0 + lc4 * 4);
        }
    };

    load_chunk(0, 0);
    CP_COMMIT();

    for (int it = 0; it < NCHUNK; ++it) {
        const int s = it & 1;
        CP_WAIT0();
        __syncthreads();
        if (it + 1 < NCHUNK) {
            load_chunk(it + 1, 1 - s);
            CP_COMMIT();
        }

        const uint32_t aS = smb + (uint32_t)(s * AS_F) * 4;
        const uint32_t bS = smb + (uint32_t)((2 + s) * AS_F) * 4;
#pragma unroll
        for (int kk = 0; kk < KC; kk += 8) {
            uint32_t a[4][4], b[2][4];
#pragma unroll
            for (int am = 0; am < 4; am++)
                LDSM_X4(a[am], aS + (uint32_t)(a_off[am] + kk) * 4);
#pragma unroll
            for (int bn = 0; bn < 2; bn++)
                LDSM_X4(b[bn], bS + (uint32_t)(b_off[bn] + kk) * 4);
#pragma unroll
            for (int am = 0; am < 4; am++)
#pragma unroll
                for (int j = 0; j < 4; j++)
                    mma_tf32(d[am][j], a[am], &b[j >> 1][(j & 1) * 2]);
        }
        __syncthreads();
    }

    // ---- epilogue: bias + sigmoid, direct stores ----
    const int g = lane >> 2, t = lane & 3;
#pragma unroll
    for (int am = 0; am < 4; am++) {
        const int r0 = row0 + wm * 64 + am * 16 + g;
#pragma unroll
        for (int j = 0; j < 4; j++) {
            const int c = col0 + wn * 32 + j * 8 + t * 2;
            const float bx = bias[c], by = bias[c + 1];
            float2 o0, o1;
            o0.x = sigmoidf_(d[am][j][0] + bx);
            o0.y = sigmoidf_(d[am][j][1] + by);
            o1.x = sigmoidf_(d[am][j][2] + bx);
            o1.y = sigmoidf_(d[am][j][3] + by);
            *(float2*)(out + (long long)r0 * D_ + c)       = o0;
            *(float2*)(out + (long long)(r0 + 8) * D_ + c) = o1;
        }
    }
}

// ---------------- launch ----------------
extern "C" void kernel_launch(void* const* d_in, const int* in_sizes, int n_in,
                              void* d_out, int out_size) {
    const float* x  = (const float*)d_in[0];
    const float* lW = (const float*)d_in[1];
    const float* lb = (const float*)d_in[2];
    const float* pW = (const float*)d_in[3];
    const float* pb = (const float*)d_in[4];
    float* out = (float*)d_out;

    {   // W tf32 rounding
        long long n4 = (long long)D_ * D_ / 4;
        int threads = 256;
        int blocks = (int)((n4 + threads - 1) / threads);
        conv_w_kernel<<<blocks, threads>>>(pW);
    }
    {   // Y build
        long long n4 = (long long)B_ * D_ / 4;
        int threads = 256;
        int blocks = (int)((n4 + threads - 1) / threads);
        compute_y_kernel<<<blocks, threads>>>(x, lW, lb);
    }
    {   // GEMM + bias + sigmoid
        cudaFuncSetAttribute(gemm_mma_kernel,
                             cudaFuncAttributeMaxDynamicSharedMemorySize, SM_BYTES);
        dim3 grid(D_ / TN, B_ / TM);   // (32, 16)
        gemm_mma_kernel<<<grid, 256, SM_BYTES>>>(pb, out);
    }
}

// round 4
// speedup vs baseline: 6.9890x; 1.7376x over previous
#include <cuda_runtime.h>
#include <cuda_fp16.h>
#include <cstdint>
#include <math.h>

#define B_  2048
#define H_  4
#define D_  4096
#define M_  8
#define DM_ 512

// ---------------- scratch (fp16 operands) ----------------
__device__ __align__(16) __half g_Yh[(size_t)B_ * D_];
__device__ __align__(16) __half g_Wh[(size_t)D_ * D_];

// ---------------- helpers ----------------
__device__ __forceinline__ uint32_t smem_u32(const void* p) {
    uint32_t a;
    asm("{ .reg .u64 t; cvta.to.shared.u64 t, %1; cvt.u32.u64 %0, t; }" : "=r"(a) : "l"(p));
    return a;
}

#define CP_ASYNC16(dst, src) \
    asm volatile("cp.async.cg.shared.global [%0], [%1], 16;" :: "r"(dst), "l"(src))
#define CP_COMMIT()  asm volatile("cp.async.commit_group;" ::: "memory")
#define CP_WAIT0()   asm volatile("cp.async.wait_group 0;" ::: "memory")

#define LDSM_X4(r, addr) \
    asm volatile("ldmatrix.sync.aligned.m8n8.x4.shared.b16 {%0,%1,%2,%3}, [%4];" \
                 : "=r"((r)[0]), "=r"((r)[1]), "=r"((r)[2]), "=r"((r)[3]) : "r"(addr))

__device__ __forceinline__ void mma_f16(float* d, const uint32_t* a, const uint32_t* b) {
    asm volatile(
        "mma.sync.aligned.m16n8k16.row.col.f32.f16.f16.f32 "
        "{%0,%1,%2,%3}, {%4,%5,%6,%7}, {%8,%9}, {%0,%1,%2,%3};"
        : "+f"(d[0]), "+f"(d[1]), "+f"(d[2]), "+f"(d[3])
        : "r"(a[0]), "r"(a[1]), "r"(a[2]), "r"(a[3]), "r"(b[0]), "r"(b[1]));
}

__device__ __forceinline__ float sigmoidf_(float v) {
    return 1.0f / (1.0f + expf(-v));
}

// ---------------- kernel 0: W fp32 -> fp16 scratch ----------------
__global__ void conv_w_kernel(const float* __restrict__ W) {
    long long i8 = (long long)blockIdx.x * blockDim.x + threadIdx.x;
    long long base = i8 * 8;
    if (base >= (long long)D_ * D_) return;
    float4 v0 = *(const float4*)(W + base);
    float4 v1 = *(const float4*)(W + base + 4);
    __half2 h[4];
    h[0] = __floats2half2_rn(v0.x, v0.y);
    h[1] = __floats2half2_rn(v0.z, v0.w);
    h[2] = __floats2half2_rn(v1.x, v1.y);
    h[3] = __floats2half2_rn(v1.z, v1.w);
    *(uint4*)(g_Wh + base) = *(uint4*)h;
}

// ---------------- kernel 1: grouped local linear -> fp16 Y ----------------
__global__ void compute_y_kernel(const float* __restrict__ x,
                                 const float* __restrict__ lW,
                                 const float* __restrict__ lb) {
    long long i8 = (long long)blockIdx.x * blockDim.x + threadIdx.x;
    long long flat = i8 * 8;
    if (flat >= (long long)B_ * D_) return;

    int c = (int)(flat % DM_);
    long long t = flat / DM_;
    int b = (int)(t % B_);
    int m = (int)(t / B_);

    float w0 = lW[m * H_ + 0], w1 = lW[m * H_ + 1];
    float w2 = lW[m * H_ + 2], w3 = lW[m * H_ + 3];
    float bb = lb[m];

    const float* xb = x + (long long)b * H_ * D_ + m * DM_ + c;
    __half2 hv[4];
#pragma unroll
    for (int q = 0; q < 2; q++) {
        float4 v0 = *(const float4*)(xb + 0ll * D_ + q * 4);
        float4 v1 = *(const float4*)(xb + 1ll * D_ + q * 4);
        float4 v2 = *(const float4*)(xb + 2ll * D_ + q * 4);
        float4 v3 = *(const float4*)(xb + 3ll * D_ + q * 4);
        float rx = fmaf(w0, v0.x, fmaf(w1, v1.x, fmaf(w2, v2.x, fmaf(w3, v3.x, bb))));
        float ry = fmaf(w0, v0.y, fmaf(w1, v1.y, fmaf(w2, v2.y, fmaf(w3, v3.y, bb))));
        float rz = fmaf(w0, v0.z, fmaf(w1, v1.z, fmaf(w2, v2.z, fmaf(w3, v3.z, bb))));
        float rw = fmaf(w0, v0.w, fmaf(w1, v1.w, fmaf(w2, v2.w, fmaf(w3, v3.w, bb))));
        hv[q * 2 + 0] = __floats2half2_rn(rx, ry);
        hv[q * 2 + 1] = __floats2half2_rn(rz, rw);
    }
    *(uint4*)(g_Yh + flat) = *(uint4*)hv;
}

// ---------------- kernel 2: fp16 mma.sync GEMM + bias + sigmoid ----------
// C[2048 x 4096] = sigmoid( Y @ W^T + bias ), NT gemm, K-contiguous operands.
#define TM      128
#define TN      128
#define KC      64                  // halves per chunk (128 B rows)
#define NCHUNK  (D_ / KC)           // 64
#define SROW    72                  // padded row stride in halves (144 B)
#define STAGE_H (128 * SROW)        // halves per operand per stage (9216)
#define SM_BYTES (4 * STAGE_H * 2)  // 73728 B

__global__ __launch_bounds__(256, 2)
void gemm_mma_kernel(const float* __restrict__ bias,
                     float* __restrict__ out) {
    extern __shared__ __half sm[];
    const uint32_t smb = smem_u32(sm);

    const int tid  = threadIdx.x;
    const int wid  = tid >> 5;
    const int lane = tid & 31;
    const int wm   = wid >> 2;     // 0..1 : 64-row slab
    const int wn   = wid & 3;      // 0..3 : 32-col slab

    const int row0 = blockIdx.y * TM;
    const int col0 = blockIdx.x * TN;

    const __half* Ag = g_Yh + (long long)row0 * D_;
    const __half* Bg = g_Wh + (long long)col0 * D_;

    // ldmatrix source offsets in halves (k-part added per step)
    int a_off[4], b_off[2];
#pragma unroll
    for (int am = 0; am < 4; am++)
        a_off[am] = (wm * 64 + am * 16 + (lane & 15)) * SROW + ((lane >> 4) << 3);
    {
        const int seg = lane >> 3;
#pragma unroll
        for (int bn = 0; bn < 2; bn++)
            b_off[bn] = (wn * 32 + bn * 16 + ((seg >> 1) << 3) + (lane & 7)) * SROW
                      + ((seg & 1) << 3);
    }

    // gmem->smem: 128 rows x 8 16B-chunks per operand, 4+4 per thread
    const int lrow = tid >> 3;     // 0..31, +32 per i
    const int lc8  = tid & 7;      // 16B chunk (8 halves)

    float d[4][4][4];
#pragma unroll
    for (int i = 0; i < 4; i++)
#pragma unroll
        for (int j = 0; j < 4; j++)
#pragma unroll
            for (int q = 0; q < 4; q++) d[i][j][q] = 0.0f;

    auto load_chunk = [&](int it, int s) {
        const int k0 = it * KC;
        const uint32_t aS = smb + (uint32_t)(s * STAGE_H) * 2;
        const uint32_t bS = smb + (uint32_t)((2 + s) * STAGE_H) * 2;
#pragma unroll
        for (int i = 0; i < 4; i++) {
            const int r = lrow + i * 32;
            CP_ASYNC16(aS + (uint32_t)(r * SROW + lc8 * 8) * 2,
                       Ag + (long long)r * D_ + k0 + lc8 * 8);
        }
#pragma unroll
        for (int i = 0; i < 4; i++) {
            const int r = lrow + i * 32;
            CP_ASYNC16(bS + (uint32_t)(r * SROW + lc8 * 8) * 2,
                       Bg + (long long)r * D_ + k0 + lc8 * 8);
        }
    };

    load_chunk(0, 0);
    CP_COMMIT();

    for (int it = 0; it < NCHUNK; ++it) {
        const int s = it & 1;
        CP_WAIT0();
        __syncthreads();
        if (it + 1 < NCHUNK) {
            load_chunk(it + 1, 1 - s);
            CP_COMMIT();
        }

        const uint32_t aS = smb + (uint32_t)(s * STAGE_H) * 2;
        const uint32_t bS = smb + (uint32_t)((2 + s) * STAGE_H) * 2;
#pragma unroll
        for (int kk = 0; kk < KC; kk += 16) {
            uint32_t a[4][4], b[2][4];
#pragma unroll
            for (int am = 0; am < 4; am++)
                LDSM_X4(a[am], aS + (uint32_t)(a_off[am] + kk) * 2);
#pragma unroll
            for (int bn = 0; bn < 2; bn++)
                LDSM_X4(b[bn], bS + (uint32_t)(b_off[bn] + kk) * 2);
#pragma unroll
            for (int am = 0; am < 4; am++)
#pragma unroll
                for (int j = 0; j < 4; j++)
                    mma_f16(d[am][j], a[am], &b[j >> 1][(j & 1) * 2]);
        }
        __syncthreads();
    }

    // epilogue: bias + sigmoid
    const int g = lane >> 2, t4 = lane & 3;
#pragma unroll
    for (int am = 0; am < 4; am++) {
        const int r0 = row0 + wm * 64 + am * 16 + g;
#pragma unroll
        for (int j = 0; j < 4; j++) {
            const int c = col0 + wn * 32 + j * 8 + t4 * 2;
            const float bx = bias[c], by = bias[c + 1];
            float2 o0, o1;
            o0.x = sigmoidf_(d[am][j][0] + bx);
            o0.y = sigmoidf_(d[am][j][1] + by);
            o1.x = sigmoidf_(d[am][j][2] + bx);
            o1.y = sigmoidf_(d[am][j][3] + by);
            *(float2*)(out + (long long)r0 * D_ + c)       = o0;
            *(float2*)(out + (long long)(r0 + 8) * D_ + c) = o1;
        }
    }
}

// ---------------- launch ----------------
extern "C" void kernel_launch(void* const* d_in, const int* in_sizes, int n_in,
                              void* d_out, int out_size) {
    const float* x  = (const float*)d_in[0];
    const float* lW = (const float*)d_in[1];
    const float* lb = (const float*)d_in[2];
    const float* pW = (const float*)d_in[3];
    const float* pb = (const float*)d_in[4];
    float* out = (float*)d_out;

    {   // W -> fp16
        long long n8 = (long long)D_ * D_ / 8;
        int threads = 256;
        int blocks = (int)((n8 + threads - 1) / threads);
        conv_w_kernel<<<blocks, threads>>>(pW);
    }
    {   // Y build -> fp16
        long long n8 = (long long)B_ * D_ / 8;
        int threads = 256;
        int blocks = (int)((n8 + threads - 1) / threads);
        compute_y_kernel<<<blocks, threads>>>(x, lW, lb);
    }
    {   // GEMM + bias + sigmoid
        cudaFuncSetAttribute(gemm_mma_kernel,
                             cudaFuncAttributeMaxDynamicSharedMemorySize, SM_BYTES);
        dim3 grid(D_ / TN, B_ / TM);   // (32, 16)
        gemm_mma_kernel<<<grid, 256, SM_BYTES>>>(pb, out);
    }
}

// round 5
// speedup vs baseline: 7.2040x; 1.0308x over previous
#include <cuda_runtime.h>
#include <cuda_fp16.h>
#include <cstdint>
#include <math.h>

#define B_  2048
#define H_  4
#define D_  4096
#define M_  8
#define DM_ 512

// ---------------- scratch (fp16 operands) ----------------
__device__ __align__(16) __half g_Yh[(size_t)B_ * D_];
__device__ __align__(16) __half g_Wh[(size_t)D_ * D_];

// ---------------- helpers ----------------
__device__ __forceinline__ uint32_t smem_u32(const void* p) {
    uint32_t a;
    asm("{ .reg .u64 t; cvta.to.shared.u64 t, %1; cvt.u32.u64 %0, t; }" : "=r"(a) : "l"(p));
    return a;
}

#define CP_ASYNC16(dst, src) \
    asm volatile("cp.async.cg.shared.global [%0], [%1], 16;" :: "r"(dst), "l"(src))
#define CP_COMMIT()  asm volatile("cp.async.commit_group;" ::: "memory")
#define CP_WAIT0()   asm volatile("cp.async.wait_group 0;" ::: "memory")

#define LDSM_X4(r, addr) \
    asm volatile("ldmatrix.sync.aligned.m8n8.x4.shared.b16 {%0,%1,%2,%3}, [%4];" \
                 : "=r"((r)[0]), "=r"((r)[1]), "=r"((r)[2]), "=r"((r)[3]) : "r"(addr))

__device__ __forceinline__ void mma_f16(float* d, const uint32_t* a, const uint32_t* b) {
    asm volatile(
        "mma.sync.aligned.m16n8k16.row.col.f32.f16.f16.f32 "
        "{%0,%1,%2,%3}, {%4,%5,%6,%7}, {%8,%9}, {%0,%1,%2,%3};"
        : "+f"(d[0]), "+f"(d[1]), "+f"(d[2]), "+f"(d[3])
        : "r"(a[0]), "r"(a[1]), "r"(a[2]), "r"(a[3]), "r"(b[0]), "r"(b[1]));
}

__device__ __forceinline__ float sigmoidf_(float v) {
    return __fdividef(1.0f, 1.0f + __expf(-v));
}

// ---------------- kernel 1: fused prologue ----------------
// Part A (first WBLK blocks): W fp32 -> fp16.
// Part B (rest):              grouped local linear -> fp16 Y.
#define WBLK ((int)(((long long)D_ * D_ / 8) / 256))   // 8192 blocks
#define YBLK ((int)(((long long)B_ * D_ / 8) / 256))   // 4096 blocks

__global__ __launch_bounds__(256)
void prologue_kernel(const float* __restrict__ W,
                     const float* __restrict__ x,
                     const float* __restrict__ lW,
                     const float* __restrict__ lb) {
    const int bid = blockIdx.x;
    if (bid < WBLK) {
        long long base = ((long long)bid * 256 + threadIdx.x) * 8;
        float4 v0 = *(const float4*)(W + base);
        float4 v1 = *(const float4*)(W + base + 4);
        __half2 h[4];
        h[0] = __floats2half2_rn(v0.x, v0.y);
        h[1] = __floats2half2_rn(v0.z, v0.w);
        h[2] = __floats2half2_rn(v1.x, v1.y);
        h[3] = __floats2half2_rn(v1.z, v1.w);
        *(uint4*)(g_Wh + base) = *(uint4*)h;
    } else {
        long long flat = ((long long)(bid - WBLK) * 256 + threadIdx.x) * 8;
        int c = (int)(flat % DM_);
        long long t = flat / DM_;
        int b = (int)(t % B_);
        int m = (int)(t / B_);

        float w0 = lW[m * H_ + 0], w1 = lW[m * H_ + 1];
        float w2 = lW[m * H_ + 2], w3 = lW[m * H_ + 3];
        float bb = lb[m];

        const float* xb = x + (long long)b * H_ * D_ + m * DM_ + c;
        __half2 hv[4];
#pragma unroll
        for (int q = 0; q < 2; q++) {
            float4 v0 = *(const float4*)(xb + 0ll * D_ + q * 4);
            float4 v1 = *(const float4*)(xb + 1ll * D_ + q * 4);
            float4 v2 = *(const float4*)(xb + 2ll * D_ + q * 4);
            float4 v3 = *(const float4*)(xb + 3ll * D_ + q * 4);
            float rx = fmaf(w0, v0.x, fmaf(w1, v1.x, fmaf(w2, v2.x, fmaf(w3, v3.x, bb))));
            float ry = fmaf(w0, v0.y, fmaf(w1, v1.y, fmaf(w2, v2.y, fmaf(w3, v3.y, bb))));
            float rz = fmaf(w0, v0.z, fmaf(w1, v1.z, fmaf(w2, v2.z, fmaf(w3, v3.z, bb))));
            float rw = fmaf(w0, v0.w, fmaf(w1, v1.w, fmaf(w2, v2.w, fmaf(w3, v3.w, bb))));
            hv[q * 2 + 0] = __floats2half2_rn(rx, ry);
            hv[q * 2 + 1] = __floats2half2_rn(rz, rw);
        }
        *(uint4*)(g_Yh + flat) = *(uint4*)hv;
    }
}

// ---------------- kernel 2: fp16 mma.sync GEMM + bias + sigmoid ----------
#define TM      128
#define TN      128
#define KC      64                  // halves per chunk (128 B rows)
#define NCHUNK  (D_ / KC)           // 64
#define SROW    72                  // padded row stride in halves (144 B)
#define STAGE_H (128 * SROW)        // halves per operand per stage (9216)
#define SM_BYTES (4 * STAGE_H * 2)  // 73728 B

__global__ __launch_bounds__(256, 2)
void gemm_mma_kernel(const float* __restrict__ bias,
                     float* __restrict__ out) {
    extern __shared__ __half sm[];
    const uint32_t smb = smem_u32(sm);

    const int tid  = threadIdx.x;
    const int wid  = tid >> 5;
    const int lane = tid & 31;
    const int wm   = wid >> 2;     // 0..1 : 64-row slab
    const int wn   = wid & 3;      // 0..3 : 32-col slab

    const int row0 = blockIdx.y * TM;
    const int col0 = blockIdx.x * TN;

    const __half* Ag = g_Yh + (long long)row0 * D_;
    const __half* Bg = g_Wh + (long long)col0 * D_;

    int a_off[4], b_off[2];
#pragma unroll
    for (int am = 0; am < 4; am++)
        a_off[am] = (wm * 64 + am * 16 + (lane & 15)) * SROW + ((lane >> 4) << 3);
    {
        const int seg = lane >> 3;
#pragma unroll
        for (int bn = 0; bn < 2; bn++)
            b_off[bn] = (wn * 32 + bn * 16 + ((seg >> 1) << 3) + (lane & 7)) * SROW
                      + ((seg & 1) << 3);
    }

    const int lrow = tid >> 3;
    const int lc8  = tid & 7;

    float d[4][4][4];
#pragma unroll
    for (int i = 0; i < 4; i++)
#pragma unroll
        for (int j = 0; j < 4; j++)
#pragma unroll
            for (int q = 0; q < 4; q++) d[i][j][q] = 0.0f;

    auto load_chunk = [&](int it, int s) {
        const int k0 = it * KC;
        const uint32_t aS = smb + (uint32_t)(s * STAGE_H) * 2;
        const uint32_t bS = smb + (uint32_t)((2 + s) * STAGE_H) * 2;
#pragma unroll
        for (int i = 0; i < 4; i++) {
            const int r = lrow + i * 32;
            CP_ASYNC16(aS + (uint32_t)(r * SROW + lc8 * 8) * 2,
                       Ag + (long long)r * D_ + k0 + lc8 * 8);
        }
#pragma unroll
        for (int i = 0; i < 4; i++) {
            const int r = lrow + i * 32;
            CP_ASYNC16(bS + (uint32_t)(r * SROW + lc8 * 8) * 2,
                       Bg + (long long)r * D_ + k0 + lc8 * 8);
        }
    };

    load_chunk(0, 0);
    CP_COMMIT();

    for (int it = 0; it < NCHUNK; ++it) {
        const int s = it & 1;
        CP_WAIT0();
        __syncthreads();
        if (it + 1 < NCHUNK) {
            load_chunk(it + 1, 1 - s);
            CP_COMMIT();
        }

        const uint32_t aS = smb + (uint32_t)(s * STAGE_H) * 2;
        const uint32_t bS = smb + (uint32_t)((2 + s) * STAGE_H) * 2;
#pragma unroll
        for (int kk = 0; kk < KC; kk += 16) {
            uint32_t a[4][4], b[2][4];
#pragma unroll
            for (int am = 0; am < 4; am++)
                LDSM_X4(a[am], aS + (uint32_t)(a_off[am] + kk) * 2);
#pragma unroll
            for (int bn = 0; bn < 2; bn++)
                LDSM_X4(b[bn], bS + (uint32_t)(b_off[bn] + kk) * 2);
#pragma unroll
            for (int am = 0; am < 4; am++)
#pragma unroll
                for (int j = 0; j < 4; j++)
                    mma_f16(d[am][j], a[am], &b[j >> 1][(j & 1) * 2]);
        }
        __syncthreads();
    }

    const int g = lane >> 2, t4 = lane & 3;
#pragma unroll
    for (int am = 0; am < 4; am++) {
        const int r0 = row0 + wm * 64 + am * 16 + g;
#pragma unroll
        for (int j = 0; j < 4; j++) {
            const int c = col0 + wn * 32 + j * 8 + t4 * 2;
            const float bx = bias[c], by = bias[c + 1];
            float2 o0, o1;
            o0.x = sigmoidf_(d[am][j][0] + bx);
            o0.y = sigmoidf_(d[am][j][1] + by);
            o1.x = sigmoidf_(d[am][j][2] + bx);
            o1.y = sigmoidf_(d[am][j][3] + by);
            *(float2*)(out + (long long)r0 * D_ + c)       = o0;
            *(float2*)(out + (long long)(r0 + 8) * D_ + c) = o1;
        }
    }
}

// ---------------- launch ----------------
extern "C" void kernel_launch(void* const* d_in, const int* in_sizes, int n_in,
                              void* d_out, int out_size) {
    const float* x  = (const float*)d_in[0];
    const float* lW = (const float*)d_in[1];
    const float* lb = (const float*)d_in[2];
    const float* pW = (const float*)d_in[3];
    const float* pb = (const float*)d_in[4];
    float* out = (float*)d_out;

    prologue_kernel<<<WBLK + YBLK, 256>>>(pW, x, lW, lb);

    cudaFuncSetAttribute(gemm_mma_kernel,
                         cudaFuncAttributeMaxDynamicSharedMemorySize, SM_BYTES);
    dim3 grid(D_ / TN, B_ / TM);   // (32, 16)
    gemm_mma_kernel<<<grid, 256, SM_BYTES>>>(pb, out);
}

// round 8
// speedup vs baseline: 7.4114x; 1.0288x over previous
#include <cuda_runtime.h>
#include <cuda_fp16.h>
#include <cstdint>
#include <math.h>

#define B_  2048
#define H_  4
#define D_  4096
#define M_  8
#define DM_ 512

// ---------------- scratch (fp16 operands) ----------------
__device__ __align__(16) __half g_Yh[(size_t)B_ * D_];
__device__ __align__(16) __half g_Wh[(size_t)D_ * D_];

// ---------------- helpers ----------------
__device__ __forceinline__ uint32_t smem_u32(const void* p) {
    uint32_t a;
    asm("{ .reg .u64 t; cvta.to.shared.u64 t, %1; cvt.u32.u64 %0, t; }" : "=r"(a) : "l"(p));
    return a;
}

#define CP_ASYNC16(dst, src) \
    asm volatile("cp.async.cg.shared.global [%0], [%1], 16;" :: "r"(dst), "l"(src))
#define CP_COMMIT()  asm volatile("cp.async.commit_group;" ::: "memory")
#define CP_WAIT1()   asm volatile("cp.async.wait_group 1;" ::: "memory")

#define LDSM_X4(r, addr) \
    asm volatile("ldmatrix.sync.aligned.m8n8.x4.shared.b16 {%0,%1,%2,%3}, [%4];" \
                 : "=r"((r)[0]), "=r"((r)[1]), "=r"((r)[2]), "=r"((r)[3]) : "r"(addr))

__device__ __forceinline__ void mma_f16(float* d, const uint32_t* a, const uint32_t* b) {
    asm volatile(
        "mma.sync.aligned.m16n8k16.row.col.f32.f16.f16.f32 "
        "{%0,%1,%2,%3}, {%4,%5,%6,%7}, {%8,%9}, {%0,%1,%2,%3};"
        : "+f"(d[0]), "+f"(d[1]), "+f"(d[2]), "+f"(d[3])
        : "r"(a[0]), "r"(a[1]), "r"(a[2]), "r"(a[3]), "r"(b[0]), "r"(b[1]));
}

__device__ __forceinline__ float sigmoidf_(float v) {
    return __fdividef(1.0f, 1.0f + __expf(-v));
}

// ---------------- kernel 1: fused prologue ----------------
#define WBLK ((int)(((long long)D_ * D_ / 8) / 256))   // 8192 blocks
#define YBLK ((int)(((long long)B_ * D_ / 8) / 256))   // 4096 blocks

__global__ __launch_bounds__(256)
void prologue_kernel(const float* __restrict__ W,
                     const float* __restrict__ x,
                     const float* __restrict__ lW,
                     const float* __restrict__ lb) {
    const int bid = blockIdx.x;
    if (bid < WBLK) {
        long long base = ((long long)bid * 256 + threadIdx.x) * 8;
        float4 v0 = *(const float4*)(W + base);
        float4 v1 = *(const float4*)(W + base + 4);
        __half2 h[4];
        h[0] = __floats2half2_rn(v0.x, v0.y);
        h[1] = __floats2half2_rn(v0.z, v0.w);
        h[2] = __floats2half2_rn(v1.x, v1.y);
        h[3] = __floats2half2_rn(v1.z, v1.w);
        *(uint4*)(g_Wh + base) = *(uint4*)h;
    } else {
        long long flat = ((long long)(bid - WBLK) * 256 + threadIdx.x) * 8;
        int c = (int)(flat % DM_);
        long long t = flat / DM_;
        int b = (int)(t % B_);
        int m = (int)(t / B_);

        float w0 = lW[m * H_ + 0], w1 = lW[m * H_ + 1];
        float w2 = lW[m * H_ + 2], w3 = lW[m * H_ + 3];
        float bb = lb[m];

        const float* xb = x + (long long)b * H_ * D_ + m * DM_ + c;
        __half2 hv[4];
#pragma unroll
        for (int q = 0; q < 2; q++) {
            float4 v0 = *(const float4*)(xb + 0ll * D_ + q * 4);
            float4 v1 = *(const float4*)(xb + 1ll * D_ + q * 4);
            float4 v2 = *(const float4*)(xb + 2ll * D_ + q * 4);
            float4 v3 = *(const float4*)(xb + 3ll * D_ + q * 4);
            float rx = fmaf(w0, v0.x, fmaf(w1, v1.x, fmaf(w2, v2.x, fmaf(w3, v3.x, bb))));
            float ry = fmaf(w0, v0.y, fmaf(w1, v1.y, fmaf(w2, v2.y, fmaf(w3, v3.y, bb))));
            float rz = fmaf(w0, v0.z, fmaf(w1, v1.z, fmaf(w2, v2.z, fmaf(w3, v3.z, bb))));
            float rw = fmaf(w0, v0.w, fmaf(w1, v1.w, fmaf(w2, v2.w, fmaf(w3, v3.w, bb))));
            hv[q * 2 + 0] = __floats2half2_rn(rx, ry);
            hv[q * 2 + 1] = __floats2half2_rn(rz, rw);
        }
        *(uint4*)(g_Yh + flat) = *(uint4*)hv;
    }
}

// ---------------- kernel 2: fp16 mma.sync GEMM, 3-stage pipeline ----------
#define TM      128
#define TN      128
#define KC      64                  // halves per chunk (128 B rows)
#define NCHUNK  (D_ / KC)           // 64
#define SROW    72                  // padded row stride in halves (144 B)
#define STAGE_H (2 * 128 * SROW)    // halves per stage, A then B (18432)
#define NSTAGE  3
#define SM_BYTES (NSTAGE * STAGE_H * 2)   // 110592 B

__global__ __launch_bounds__(256, 2)
void gemm_mma_kernel(const float* __restrict__ bias,
                     float* __restrict__ out) {
    extern __shared__ __half sm[];
    const uint32_t smb = smem_u32(sm);

    const int tid  = threadIdx.x;
    const int wid  = tid >> 5;
    const int lane = tid & 31;
    const int wm   = wid >> 2;     // 0..1
    const int wn   = wid & 3;      // 0..3

    const int row0 = blockIdx.y * TM;
    const int col0 = blockIdx.x * TN;

    const __half* Ag = g_Yh + (long long)row0 * D_;
    const __half* Bg = g_Wh + (long long)col0 * D_;

    uint32_t stage_base[NSTAGE];
#pragma unroll
    for (int s = 0; s < NSTAGE; s++) stage_base[s] = smb + (uint32_t)(s * STAGE_H) * 2;

    int a_off[4], b_off[2];
#pragma unroll
    for (int am = 0; am < 4; am++)
        a_off[am] = (wm * 64 + am * 16 + (lane & 15)) * SROW + ((lane >> 4) << 3);
    {
        const int seg = lane >> 3;
#pragma unroll
        for (int bn = 0; bn < 2; bn++)
            b_off[bn] = (128 + wn * 32 + bn * 16 + ((seg >> 1) << 3) + (lane & 7)) * SROW
                      + ((seg & 1) << 3);
    }

    const int lrow = tid >> 3;     // 0..31, +32 per i
    const int lc8  = tid & 7;

    float d[4][4][4];
#pragma unroll
    for (int i = 0; i < 4; i++)
#pragma unroll
        for (int j = 0; j < 4; j++)
#pragma unroll
            for (int q = 0; q < 4; q++) d[i][j][q] = 0.0f;

    auto load_chunk = [&](int it, int s) {
        const int k0 = it * KC;
        const uint32_t aS = stage_base[s];
        const uint32_t bS = stage_base[s] + (uint32_t)(128 * SROW) * 2;
#pragma unroll
        for (int i = 0; i < 4; i++) {
            const int r = lrow + i * 32;
            CP_ASYNC16(aS + (uint32_t)(r * SROW + lc8 * 8) * 2,
                       Ag + (long long)r * D_ + k0 + lc8 * 8);
        }
#pragma unroll
        for (int i = 0; i < 4; i++) {
            const int r = lrow + i * 32;
            CP_ASYNC16(bS + (uint32_t)(r * SROW + lc8 * 8) * 2,
                       Bg + (long long)r * D_ + k0 + lc8 * 8);
        }
    };

    // prologue: chunks 0 and 1 in flight
    load_chunk(0, 0);
    CP_COMMIT();
    load_chunk(1, 1);
    CP_COMMIT();

    int s = 0;
    for (int it = 0; it < NCHUNK; ++it) {
        CP_WAIT1();            // chunk `it` resident; `it+1` may be in flight
        __syncthreads();       // all warps past last read of the stage we refill

        if (it + 2 < NCHUNK) {
            int s2 = s + 2; if (s2 >= NSTAGE) s2 -= NSTAGE;
            load_chunk(it + 2, s2);
        }
        CP_COMMIT();           // one group per iteration (may be empty)

        const uint32_t base = stage_base[s];
#pragma unroll
        for (int kk = 0; kk < KC; kk += 16) {
            uint32_t a[4][4], b[2][4];
#pragma unroll
            for (int am = 0; am < 4; am++)
                LDSM_X4(a[am], base + (uint32_t)(a_off[am] + kk) * 2);
#pragma unroll
            for (int bn = 0; bn < 2; bn++)
                LDSM_X4(b[bn], base + (uint32_t)(b_off[bn] + kk) * 2);
#pragma unroll
            for (int am = 0; am < 4; am++)
#pragma unroll
                for (int j = 0; j < 4; j++)
                    mma_f16(d[am][j], a[am], &b[j >> 1][(j & 1) * 2]);
        }
        if (++s >= NSTAGE) s = 0;
    }

    // epilogue: bias + sigmoid
    const int g = lane >> 2, t4 = lane & 3;
#pragma unroll
    for (int am = 0; am < 4; am++) {
        const int r0 = row0 + wm * 64 + am * 16 + g;
#pragma unroll
        for (int j = 0; j < 4; j++) {
            const int c = col0 + wn * 32 + j * 8 + t4 * 2;
            const float bx = bias[c], by = bias[c + 1];
            float2 o0, o1;
            o0.x = sigmoidf_(d[am][j][0] + bx);
            o0.y = sigmoidf_(d[am][j][1] + by);
            o1.x = sigmoidf_(d[am][j][2] + bx);
            o1.y = sigmoidf_(d[am][j][3] + by);
            *(float2*)(out + (long long)r0 * D_ + c)       = o0;
            *(float2*)(out + (long long)(r0 + 8) * D_ + c) = o1;
        }
    }
}

// ---------------- launch ----------------
extern "C" void kernel_launch(void* const* d_in, const int* in_sizes, int n_in,
                              void* d_out, int out_size) {
    const float* x  = (const float*)d_in[0];
    const float* lW = (const float*)d_in[1];
    const float* lb = (const float*)d_in[2];
    const float* pW = (const float*)d_in[3];
    const float* pb = (const float*)d_in[4];
    float* out = (float*)d_out;

    prologue_kernel<<<WBLK + YBLK, 256>>>(pW, x, lW, lb);

    cudaFuncSetAttribute(gemm_mma_kernel,
                         cudaFuncAttributeMaxDynamicSharedMemorySize, SM_BYTES);
    dim3 grid(D_ / TN, B_ / TM);   // (32, 16)
    gemm_mma_kernel<<<grid, 256, SM_BYTES>>>(pb, out);
}

// round 9
// speedup vs baseline: 7.6487x; 1.0320x over previous
#include <cuda_runtime.h>
#include <cuda_fp16.h>
#include <cstdint>
#include <math.h>

#define B_  2048
#define H_  4
#define D_  4096
#define M_  8
#define DM_ 512

// ---------------- scratch (fp16 operands) ----------------
__device__ __align__(16) __half g_Yh[(size_t)B_ * D_];
__device__ __align__(16) __half g_Wh[(size_t)D_ * D_];

// ---------------- helpers ----------------
__device__ __forceinline__ uint32_t smem_u32(const void* p) {
    uint32_t a;
    asm("{ .reg .u64 t; cvta.to.shared.u64 t, %1; cvt.u32.u64 %0, t; }" : "=r"(a) : "l"(p));
    return a;
}

#define CP_ASYNC16(dst, src) \
    asm volatile("cp.async.cg.shared.global [%0], [%1], 16;" :: "r"(dst), "l"(src))
#define CP_COMMIT()  asm volatile("cp.async.commit_group;" ::: "memory")
#define CP_WAIT1()   asm volatile("cp.async.wait_group 1;" ::: "memory")

#define LDSM_X4(r, addr) \
    asm volatile("ldmatrix.sync.aligned.m8n8.x4.shared.b16 {%0,%1,%2,%3}, [%4];" \
                 : "=r"((r)[0]), "=r"((r)[1]), "=r"((r)[2]), "=r"((r)[3]) : "r"(addr))

__device__ __forceinline__ void mma_f16(float* d, const uint32_t* a, const uint32_t* b) {
    asm volatile(
        "mma.sync.aligned.m16n8k16.row.col.f32.f16.f16.f32 "
        "{%0,%1,%2,%3}, {%4,%5,%6,%7}, {%8,%9}, {%0,%1,%2,%3};"
        : "+f"(d[0]), "+f"(d[1]), "+f"(d[2]), "+f"(d[3])
        : "r"(a[0]), "r"(a[1]), "r"(a[2]), "r"(a[3]), "r"(b[0]), "r"(b[1]));
}

__device__ __forceinline__ float sigmoidf_(float v) {
    return __fdividef(1.0f, 1.0f + __expf(-v));
}

// ---------------- kernel 1: fused prologue ----------------
#define WBLK ((int)(((long long)D_ * D_ / 8) / 256))   // 8192 blocks
#define YBLK ((int)(((long long)B_ * D_ / 8) / 256))   // 4096 blocks

__global__ __launch_bounds__(256)
void prologue_kernel(const float* __restrict__ W,
                     const float* __restrict__ x,
                     const float* __restrict__ lW,
                     const float* __restrict__ lb) {
    const int bid = blockIdx.x;
    if (bid < WBLK) {
        long long base = ((long long)bid * 256 + threadIdx.x) * 8;
        float4 v0 = *(const float4*)(W + base);
        float4 v1 = *(const float4*)(W + base + 4);
        __half2 h[4];
        h[0] = __floats2half2_rn(v0.x, v0.y);
        h[1] = __floats2half2_rn(v0.z, v0.w);
        h[2] = __floats2half2_rn(v1.x, v1.y);
        h[3] = __floats2half2_rn(v1.z, v1.w);
        *(uint4*)(g_Wh + base) = *(uint4*)h;
    } else {
        long long flat = ((long long)(bid - WBLK) * 256 + threadIdx.x) * 8;
        int c = (int)(flat % DM_);
        long long t = flat / DM_;
        int b = (int)(t % B_);
        int m = (int)(t / B_);

        float w0 = lW[m * H_ + 0], w1 = lW[m * H_ + 1];
        float w2 = lW[m * H_ + 2], w3 = lW[m * H_ + 3];
        float bb = lb[m];

        const float* xb = x + (long long)b * H_ * D_ + m * DM_ + c;
        __half2 hv[4];
#pragma unroll
        for (int q = 0; q < 2; q++) {
            float4 v0 = *(const float4*)(xb + 0ll * D_ + q * 4);
            float4 v1 = *(const float4*)(xb + 1ll * D_ + q * 4);
            float4 v2 = *(const float4*)(xb + 2ll * D_ + q * 4);
            float4 v3 = *(const float4*)(xb + 3ll * D_ + q * 4);
            float rx = fmaf(w0, v0.x, fmaf(w1, v1.x, fmaf(w2, v2.x, fmaf(w3, v3.x, bb))));
            float ry = fmaf(w0, v0.y, fmaf(w1, v1.y, fmaf(w2, v2.y, fmaf(w3, v3.y, bb))));
            float rz = fmaf(w0, v0.z, fmaf(w1, v1.z, fmaf(w2, v2.z, fmaf(w3, v3.z, bb))));
            float rw = fmaf(w0, v0.w, fmaf(w1, v1.w, fmaf(w2, v2.w, fmaf(w3, v3.w, bb))));
            hv[q * 2 + 0] = __floats2half2_rn(rx, ry);
            hv[q * 2 + 1] = __floats2half2_rn(rz, rw);
        }
        *(uint4*)(g_Yh + flat) = *(uint4*)hv;
    }
}

// ---------------- kernel 2: fp16 mma GEMM, 64x64 warp tile ----------------
#define TM      128
#define TN      128
#define KC      64                  // halves per chunk (128 B rows)
#define NCHUNK  (D_ / KC)           // 64
#define SROW    72                  // padded row stride in halves (144 B)
#define STAGE_H (2 * 128 * SROW)    // halves per stage, A then B (18432)
#define NSTAGE  3
#define SM_BYTES (NSTAGE * STAGE_H * 2)   // 110592 B
#define NTHR    128

__global__ __launch_bounds__(NTHR, 2)
void gemm_mma_kernel(const float* __restrict__ bias,
                     float* __restrict__ out) {
    extern __shared__ __half sm[];
    const uint32_t smb = smem_u32(sm);

    const int tid  = threadIdx.x;
    const int wid  = tid >> 5;
    const int lane = tid & 31;
    const int wm   = wid >> 1;     // 0..1 : 64-row slab
    const int wn   = wid & 1;      // 0..1 : 64-col slab

    const int row0 = blockIdx.y * TM;
    const int col0 = blockIdx.x * TN;

    const __half* Ag = g_Yh + (long long)row0 * D_;
    const __half* Bg = g_Wh + (long long)col0 * D_;

    uint32_t stage_base[NSTAGE];
#pragma unroll
    for (int s = 0; s < NSTAGE; s++) stage_base[s] = smb + (uint32_t)(s * STAGE_H) * 2;

    // ldmatrix offsets (halves; k added per step)
    int a_off[4], b_off[4];
#pragma unroll
    for (int am = 0; am < 4; am++)
        a_off[am] = (wm * 64 + am * 16 + (lane & 15)) * SROW + ((lane >> 4) << 3);
    {
        const int seg = lane >> 3;
#pragma unroll
        for (int bn = 0; bn < 4; bn++)
            b_off[bn] = (128 + wn * 64 + bn * 16 + ((seg >> 1) << 3) + (lane & 7)) * SROW
                      + ((seg & 1) << 3);
    }

    // gmem->smem: 128 rows x 8 16B-chunks per operand / 128 threads = 8+8 each
    const int lrow = tid >> 3;     // 0..15, +16 per i
    const int lc8  = tid & 7;

    float d[4][8][4];
#pragma unroll
    for (int i = 0; i < 4; i++)
#pragma unroll
        for (int j = 0; j < 8; j++)
#pragma unroll
            for (int q = 0; q < 4; q++) d[i][j][q] = 0.0f;

    auto load_chunk = [&](int it, int s) {
        const int k0 = it * KC;
        const uint32_t aS = stage_base[s];
        const uint32_t bS = stage_base[s] + (uint32_t)(128 * SROW) * 2;
#pragma unroll
        for (int i = 0; i < 8; i++) {
            const int r = lrow + i * 16;
            CP_ASYNC16(aS + (uint32_t)(r * SROW + lc8 * 8) * 2,
                       Ag + (long long)r * D_ + k0 + lc8 * 8);
        }
#pragma unroll
        for (int i = 0; i < 8; i++) {
            const int r = lrow + i * 16;
            CP_ASYNC16(bS + (uint32_t)(r * SROW + lc8 * 8) * 2,
                       Bg + (long long)r * D_ + k0 + lc8 * 8);
        }
    };

    load_chunk(0, 0);
    CP_COMMIT();
    load_chunk(1, 1);
    CP_COMMIT();

    uint32_t a[2][4][4], b[2][4][4];

    int s = 0;
    for (int it = 0; it < NCHUNK; ++it) {
        CP_WAIT1();            // chunk `it` resident
        __syncthreads();

        if (it + 2 < NCHUNK) {
            int s2 = s + 2; if (s2 >= NSTAGE) s2 -= NSTAGE;
            load_chunk(it + 2, s2);
        }
        CP_COMMIT();

        const uint32_t base = stage_base[s];

        // fragment prologue: kk=0 into buffer 0
#pragma unroll
        for (int am = 0; am < 4; am++)
            LDSM_X4(a[0][am], base + (uint32_t)a_off[am] * 2);
#pragma unroll
        for (int bn = 0; bn < 4; bn++)
            LDSM_X4(b[0][bn], base + (uint32_t)b_off[bn] * 2);

#pragma unroll
        for (int kk4 = 0; kk4 < 4; kk4++) {
            const int cur = kk4 & 1;
            if (kk4 < 3) {       // prefetch next kk fragments into alt buffer
                const int kn = (kk4 + 1) * 16;
#pragma unroll
                for (int am = 0; am < 4; am++)
                    LDSM_X4(a[cur ^ 1][am], base + (uint32_t)(a_off[am] + kn) * 2);
#pragma unroll
                for (int bn = 0; bn < 4; bn++)
                    LDSM_X4(b[cur ^ 1][bn], base + (uint32_t)(b_off[bn] + kn) * 2);
            }
#pragma unroll
            for (int am = 0; am < 4; am++)
#pragma unroll
                for (int j = 0; j < 8; j++)
                    mma_f16(d[am][j], a[cur][am], &b[cur][j >> 1][(j & 1) * 2]);
        }
        if (++s >= NSTAGE) s = 0;
    }

    // epilogue: bias + sigmoid
    const int g = lane >> 2, t4 = lane & 3;
#pragma unroll
    for (int am = 0; am < 4; am++) {
        const int r0 = row0 + wm * 64 + am * 16 + g;
#pragma unroll
        for (int j = 0; j < 8; j++) {
            const int c = col0 + wn * 64 + j * 8 + t4 * 2;
            const float bx = bias[c], by = bias[c + 1];
            float2 o0, o1;
            o0.x = sigmoidf_(d[am][j][0] + bx);
            o0.y = sigmoidf_(d[am][j][1] + by);
            o1.x = sigmoidf_(d[am][j][2] + bx);
            o1.y = sigmoidf_(d[am][j][3] + by);
            *(float2*)(out + (long long)r0 * D_ + c)       = o0;
            *(float2*)(out + (long long)(r0 + 8) * D_ + c) = o1;
        }
    }
}

// ---------------- launch ----------------
extern "C" void kernel_launch(void* const* d_in, const int* in_sizes, int n_in,
                              void* d_out, int out_size) {
    const float* x  = (const float*)d_in[0];
    const float* lW = (const float*)d_in[1];
    const float* lb = (const float*)d_in[2];
    const float* pW = (const float*)d_in[3];
    const float* pb = (const float*)d_in[4];
    float* out = (float*)d_out;

    prologue_kernel<<<WBLK + YBLK, 256>>>(pW, x, lW, lb);

    cudaFuncSetAttribute(gemm_mma_kernel,
                         cudaFuncAttributeMaxDynamicSharedMemorySize, SM_BYTES);
    dim3 grid(D_ / TN, B_ / TM);   // (32, 16)
    gemm_mma_kernel<<<grid, NTHR, SM_BYTES>>>(pb, out);
}